// round 5
// baseline (speedup 1.0000x reference)
#include <cuda_runtime.h>

#define NNODES 150000
#define MAXE   2000000
#define EMB4   32          // 128 floats = 32 float4 per row
#define MAXB   16384
#define MAXROWS (2*MAXB)

// ---------------- static device scratch -------------------------------------
__device__ float4 g_h0[NNODES * EMB4];
__device__ float4 g_h1[NNODES * EMB4];
__device__ float4 g_h2[NNODES * EMB4];
__device__ float4 g_h3[NNODES * EMB4];   // layer 3: only sampled rows written
__device__ int    g_cnt[NNODES];
__device__ int    g_rowptr[NNODES + 1];
__device__ int    g_cursor[NNODES];
__device__ int2   g_edge[MAXE];          // CSR {col, val-bits}
__device__ unsigned char g_need[NNODES];
__device__ int    g_rows[MAXROWS];
__device__ int    g_nrows;

// device-side layer buffer select (host cannot take addresses of __device__ arrays!)
__device__ __forceinline__ float4* layer_buf(int i) {
    return (i == 0) ? g_h0 : (i == 1) ? g_h1 : (i == 2) ? g_h2 : g_h3;
}

// ---------------- CSR build --------------------------------------------------

__global__ void k_zero(int n) {
    int i = blockIdx.x * blockDim.x + threadIdx.x;
    if (i < n) { g_cnt[i] = 0; g_need[i] = 0; }
    if (i == 0) g_nrows = 0;
}

__global__ void k_hist(const int* __restrict__ row, int e) {
    int i = blockIdx.x * blockDim.x + threadIdx.x;
    if (i < e) atomicAdd(&g_cnt[row[i]], 1);
}

// single-block fused exclusive scan over g_cnt -> g_rowptr, g_cursor
__global__ void k_scan(int n) {
    __shared__ int sh[1024];
    int chunk = (n + 1023) / 1024;
    int s = threadIdx.x * chunk;
    int e = min(s + chunk, n);
    int sum = 0;
    for (int i = s; i < e; i++) sum += g_cnt[i];
    sh[threadIdx.x] = sum;
    __syncthreads();
    for (int off = 1; off < 1024; off <<= 1) {
        int t = (threadIdx.x >= off) ? sh[threadIdx.x - off] : 0;
        __syncthreads();
        sh[threadIdx.x] += t;
        __syncthreads();
    }
    int run = sh[threadIdx.x] - sum;   // exclusive prefix
    for (int i = s; i < e; i++) {
        int c = g_cnt[i];
        g_rowptr[i] = run;
        g_cursor[i] = run;
        run += c;
    }
    if (threadIdx.x == 1023) g_rowptr[n] = run;
}

__global__ void k_fill(const int* __restrict__ row, const int* __restrict__ col,
                       const float* __restrict__ val, int e) {
    int i = blockIdx.x * blockDim.x + threadIdx.x;
    if (i < e) {
        int r = row[i];
        int p = atomicAdd(&g_cursor[r], 1);
        g_edge[p] = make_int2(col[i], __float_as_int(val[i]));
    }
}

// h0 = concat(uEmbd, iEmbd) — pure streaming copy (profiled slot: DRAM BW ref)
__global__ void k_init_h0(const float4* __restrict__ uE, const float4* __restrict__ iE,
                          int userNum, int n) {
    int i = blockIdx.x * blockDim.x + threadIdx.x;
    int total = n * EMB4;
    if (i < total) {
        int node = i >> 5;
        g_h0[i] = (node < userNum) ? uE[i] : iE[i - userNum * EMB4];
    }
}

// ---------------- SpMM core --------------------------------------------------
// Warp per row. Broadcast edge loads (all lanes read same g_edge[j]) + manual
// 4-edge unroll: 4 independent float4 gathers in flight per warp (MLP>=4).
__device__ __forceinline__ float4 row_gather(const float4* __restrict__ hin,
                                             int s, int e, int lane) {
    float4 acc = make_float4(0.f, 0.f, 0.f, 0.f);
    int j = s;
    for (; j + 4 <= e; j += 4) {
        int2 e0 = g_edge[j];
        int2 e1 = g_edge[j + 1];
        int2 e2 = g_edge[j + 2];
        int2 e3 = g_edge[j + 3];
        float4 x0 = hin[(size_t)e0.x * EMB4 + lane];
        float4 x1 = hin[(size_t)e1.x * EMB4 + lane];
        float4 x2 = hin[(size_t)e2.x * EMB4 + lane];
        float4 x3 = hin[(size_t)e3.x * EMB4 + lane];
        float v0 = __int_as_float(e0.y), v1 = __int_as_float(e1.y);
        float v2 = __int_as_float(e2.y), v3 = __int_as_float(e3.y);
        acc.x = fmaf(v0, x0.x, acc.x); acc.y = fmaf(v0, x0.y, acc.y);
        acc.z = fmaf(v0, x0.z, acc.z); acc.w = fmaf(v0, x0.w, acc.w);
        acc.x = fmaf(v1, x1.x, acc.x); acc.y = fmaf(v1, x1.y, acc.y);
        acc.z = fmaf(v1, x1.z, acc.z); acc.w = fmaf(v1, x1.w, acc.w);
        acc.x = fmaf(v2, x2.x, acc.x); acc.y = fmaf(v2, x2.y, acc.y);
        acc.z = fmaf(v2, x2.z, acc.z); acc.w = fmaf(v2, x2.w, acc.w);
        acc.x = fmaf(v3, x3.x, acc.x); acc.y = fmaf(v3, x3.y, acc.y);
        acc.z = fmaf(v3, x3.z, acc.z); acc.w = fmaf(v3, x3.w, acc.w);
    }
    for (; j < e; j++) {
        int2 ed = g_edge[j];
        float4 x = hin[(size_t)ed.x * EMB4 + lane];
        float v = __int_as_float(ed.y);
        acc.x = fmaf(v, x.x, acc.x); acc.y = fmaf(v, x.y, acc.y);
        acc.z = fmaf(v, x.z, acc.z); acc.w = fmaf(v, x.w, acc.w);
    }
    return acc;
}

// stage-selected full SpMM: layer_buf(stage) -> layer_buf(stage+1)
__global__ void k_spmm(int stage, int n) {
    const float4* hin = layer_buf(stage);
    float4*      hout = layer_buf(stage + 1);
    int w    = (blockIdx.x * blockDim.x + threadIdx.x) >> 5;
    int lane = threadIdx.x & 31;
    if (w >= n) return;
    hout[(size_t)w * EMB4 + lane] = row_gather(hin, g_rowptr[w], g_rowptr[w + 1], lane);
}

// layer 3 restricted to compacted sampled rows: g_h2 -> g_h3
__global__ void k_spmm_rows() {
    int w    = (blockIdx.x * blockDim.x + threadIdx.x) >> 5;
    int lane = threadIdx.x & 31;
    if (w >= g_nrows) return;
    int r = g_rows[w];
    g_h3[(size_t)r * EMB4 + lane] = row_gather(g_h2, g_rowptr[r], g_rowptr[r + 1], lane);
}

// ---------------- needed-row marking / compaction ----------------------------

__global__ void k_mark(const int* __restrict__ uIdx, const int* __restrict__ vIdx,
                       int userNum, int B) {
    int i = blockIdx.x * blockDim.x + threadIdx.x;
    if (i < B) {
        g_need[uIdx[i]] = 1;
        g_need[vIdx[i] + userNum] = 1;
    }
}

__global__ void k_compact(int n) {
    int i = blockIdx.x * blockDim.x + threadIdx.x;
    int lane = threadIdx.x & 31;
    int flag = (i < n) ? (int)g_need[i] : 0;
    unsigned m = __ballot_sync(0xffffffffu, flag);
    int cnt = __popc(m);
    if (cnt == 0) return;
    int base = 0;
    if (lane == 0) base = atomicAdd(&g_nrows, cnt);
    base = __shfl_sync(0xffffffffu, base, 0);
    if (flag) g_rows[base + __popc(m & ((1u << lane) - 1u))] = i;
}

// ---------------- final dot ---------------------------------------------------

__global__ void k_dot(const int* __restrict__ uIdx, const int* __restrict__ vIdx,
                      int userNum, int B, float* __restrict__ out) {
    int w    = (blockIdx.x * blockDim.x + threadIdx.x) >> 5;
    int lane = threadIdx.x & 31;
    if (w >= B) return;

    int u = uIdx[w];
    int v = vIdx[w] + userNum;
    size_t ub = (size_t)u * EMB4 + lane;
    size_t vb = (size_t)v * EMB4 + lane;

    float4 a0 = g_h0[ub], a1 = g_h1[ub], a2 = g_h2[ub], a3 = g_h3[ub];
    float4 b0 = g_h0[vb], b1 = g_h1[vb], b2 = g_h2[vb], b3 = g_h3[vb];

    float sux = a0.x + a1.x + a2.x + a3.x, svx = b0.x + b1.x + b2.x + b3.x;
    float suy = a0.y + a1.y + a2.y + a3.y, svy = b0.y + b1.y + b2.y + b3.y;
    float suz = a0.z + a1.z + a2.z + a3.z, svz = b0.z + b1.z + b2.z + b3.z;
    float suw = a0.w + a1.w + a2.w + a3.w, svw = b0.w + b1.w + b2.w + b3.w;

    float d = sux * svx + suy * svy + suz * svz + suw * svw;
    #pragma unroll
    for (int off = 16; off > 0; off >>= 1)
        d += __shfl_xor_sync(0xffffffffu, d, off);

    if (lane == 0) out[w] = d * 0.0625f;   // (1/4)*(1/4)
}

// ---------------- launch ------------------------------------------------------

extern "C" void kernel_launch(void* const* d_in, const int* in_sizes, int n_in,
                              void* d_out, int out_size) {
    const float4* uE   = (const float4*)d_in[0];
    const float4* iE   = (const float4*)d_in[1];
    const float*  Lval = (const float*)d_in[2];
    const int*    Lrow = (const int*)d_in[3];
    const int*    Lcol = (const int*)d_in[4];
    const int*    uIdx = (const int*)d_in[5];
    const int*    vIdx = (const int*)d_in[6];
    float*        out  = (float*)d_out;

    int userNum = in_sizes[0] / 128;
    int itemNum = in_sizes[1] / 128;
    int n = userNum + itemNum;
    if (n > NNODES) n = NNODES;
    int e = in_sizes[2];
    if (e > MAXE) e = MAXE;
    int B = in_sizes[5];
    if (B > MAXB) B = MAXB;

    // slot 3 (profiled) = k_init_h0: pure streaming copy -> DRAM BW reference
    k_zero   <<<(n + 255) / 256, 256>>>(n);                        // 0
    k_hist   <<<(e + 255) / 256, 256>>>(Lrow, e);                  // 1
    k_scan   <<<1, 1024>>>(n);                                     // 2
    k_init_h0<<<(n * EMB4 + 255) / 256, 256>>>(uE, iE, userNum, n);// 3  <- profiled
    k_fill   <<<(e + 255) / 256, 256>>>(Lrow, Lcol, Lval, e);      // 4

    int spmm_blocks = (n + 7) / 8;
    k_spmm<<<spmm_blocks, 256>>>(0, n);                            // 5
    k_spmm<<<spmm_blocks, 256>>>(1, n);                            // 6

    k_mark     <<<(B + 255) / 256, 256>>>(uIdx, vIdx, userNum, B); // 7
    k_compact  <<<(n + 255) / 256, 256>>>(n);                      // 8
    k_spmm_rows<<<(MAXROWS + 7) / 8, 256>>>();                     // 9

    k_dot<<<(B + 7) / 8, 256>>>(uIdx, vIdx, userNum, B, out);      // 10
}

// round 6
// speedup vs baseline: 1.0244x; 1.0244x over previous
#include <cuda_runtime.h>

#define NNODES 150000
#define MAXE   2000000
#define EMB4   32          // 128 floats = 32 float4 per row
#define MAXB   16384
#define MAXROWS (2*MAXB)

// ---------------- static device scratch -------------------------------------
__device__ float4 g_h0[NNODES * EMB4];
__device__ float4 g_h1[NNODES * EMB4];
__device__ float4 g_h2[NNODES * EMB4];
__device__ float4 g_h3[NNODES * EMB4];   // layer 3: only sampled rows written
__device__ int    g_cnt[NNODES];
__device__ int    g_rowptr[NNODES + 1];
__device__ int    g_cursor[NNODES];
__device__ int2   g_edge[MAXE];          // CSR {col, val-bits}
__device__ unsigned char g_need[NNODES];
__device__ int    g_rows[MAXROWS];
__device__ int    g_nrows;

// device-side layer buffer select
__device__ __forceinline__ float4* layer_buf(int i) {
    return (i == 0) ? g_h0 : (i == 1) ? g_h1 : (i == 2) ? g_h2 : g_h3;
}

// ---------------- CSR build --------------------------------------------------

__global__ void k_zero(int n) {
    int i = blockIdx.x * blockDim.x + threadIdx.x;
    if (i < n) { g_cnt[i] = 0; g_need[i] = 0; }
    if (i == 0) g_nrows = 0;
}

__global__ void k_hist(const int* __restrict__ row, int e) {
    int i = blockIdx.x * blockDim.x + threadIdx.x;
    if (i < e) atomicAdd(&g_cnt[row[i]], 1);
}

// single-block fused exclusive scan over g_cnt -> g_rowptr, g_cursor
__global__ void k_scan(int n) {
    __shared__ int sh[1024];
    int chunk = (n + 1023) / 1024;
    int s = threadIdx.x * chunk;
    int e = min(s + chunk, n);
    int sum = 0;
    for (int i = s; i < e; i++) sum += g_cnt[i];
    sh[threadIdx.x] = sum;
    __syncthreads();
    for (int off = 1; off < 1024; off <<= 1) {
        int t = (threadIdx.x >= off) ? sh[threadIdx.x - off] : 0;
        __syncthreads();
        sh[threadIdx.x] += t;
        __syncthreads();
    }
    int run = sh[threadIdx.x] - sum;   // exclusive prefix
    for (int i = s; i < e; i++) {
        int c = g_cnt[i];
        g_rowptr[i] = run;
        g_cursor[i] = run;
        run += c;
    }
    if (threadIdx.x == 1023) g_rowptr[n] = run;
}

__global__ void k_fill(const int* __restrict__ row, const int* __restrict__ col,
                       const float* __restrict__ val, int e) {
    int i = blockIdx.x * blockDim.x + threadIdx.x;
    if (i < e) {
        int r = row[i];
        int p = atomicAdd(&g_cursor[r], 1);
        g_edge[p] = make_int2(col[i], __float_as_int(val[i]));
    }
}

// h0 = concat(uEmbd, iEmbd) — pure streaming copy
__global__ void k_init_h0(const float4* __restrict__ uE, const float4* __restrict__ iE,
                          int userNum, int n) {
    int i = blockIdx.x * blockDim.x + threadIdx.x;
    int total = n * EMB4;
    if (i < total) {
        int node = i >> 5;
        g_h0[i] = (node < userNum) ? uE[i] : iE[i - userNum * EMB4];
    }
}

// ---------------- SpMM core (R1-proven shfl loop) -----------------------------
// Warp per row: lanes cooperatively load 32 edges coalesced, then broadcast
// each edge via shfl; all 32 lanes gather one float4 of the source row.
__device__ __forceinline__ float4 row_gather(const float4* __restrict__ hin,
                                             int s, int e, int lane) {
    float4 acc = make_float4(0.f, 0.f, 0.f, 0.f);
    for (int base = s; base < e; base += 32) {
        int idx = base + lane;
        int2 ed = (idx < e) ? g_edge[idx] : make_int2(0, 0);
        int m = min(32, e - base);
        #pragma unroll 4
        for (int j = 0; j < m; j++) {
            int   cj = __shfl_sync(0xffffffffu, ed.x, j);
            float vj = __shfl_sync(0xffffffffu, __int_as_float(ed.y), j);
            float4 x = hin[(size_t)cj * EMB4 + lane];
            acc.x = fmaf(vj, x.x, acc.x);
            acc.y = fmaf(vj, x.y, acc.y);
            acc.z = fmaf(vj, x.z, acc.z);
            acc.w = fmaf(vj, x.w, acc.w);
        }
    }
    return acc;
}

// stage-selected full SpMM: layer_buf(stage) -> layer_buf(stage+1)
__global__ void k_spmm(int stage, int n) {
    const float4* hin = layer_buf(stage);
    float4*      hout = layer_buf(stage + 1);
    int w    = (blockIdx.x * blockDim.x + threadIdx.x) >> 5;
    int lane = threadIdx.x & 31;
    if (w >= n) return;
    hout[(size_t)w * EMB4 + lane] = row_gather(hin, g_rowptr[w], g_rowptr[w + 1], lane);
}

// layer 3 restricted to compacted sampled rows: g_h2 -> g_h3
__global__ void k_spmm_rows() {
    int w    = (blockIdx.x * blockDim.x + threadIdx.x) >> 5;
    int lane = threadIdx.x & 31;
    if (w >= g_nrows) return;
    int r = g_rows[w];
    g_h3[(size_t)r * EMB4 + lane] = row_gather(g_h2, g_rowptr[r], g_rowptr[r + 1], lane);
}

// ---------------- needed-row marking / compaction ----------------------------

__global__ void k_mark(const int* __restrict__ uIdx, const int* __restrict__ vIdx,
                       int userNum, int B) {
    int i = blockIdx.x * blockDim.x + threadIdx.x;
    if (i < B) {
        g_need[uIdx[i]] = 1;
        g_need[vIdx[i] + userNum] = 1;
    }
}

__global__ void k_compact(int n) {
    int i = blockIdx.x * blockDim.x + threadIdx.x;
    int lane = threadIdx.x & 31;
    int flag = (i < n) ? (int)g_need[i] : 0;
    unsigned m = __ballot_sync(0xffffffffu, flag);
    int cnt = __popc(m);
    if (cnt == 0) return;
    int base = 0;
    if (lane == 0) base = atomicAdd(&g_nrows, cnt);
    base = __shfl_sync(0xffffffffu, base, 0);
    if (flag) g_rows[base + __popc(m & ((1u << lane) - 1u))] = i;
}

// ---------------- final dot ---------------------------------------------------

__global__ void k_dot(const int* __restrict__ uIdx, const int* __restrict__ vIdx,
                      int userNum, int B, float* __restrict__ out) {
    int w    = (blockIdx.x * blockDim.x + threadIdx.x) >> 5;
    int lane = threadIdx.x & 31;
    if (w >= B) return;

    int u = uIdx[w];
    int v = vIdx[w] + userNum;
    size_t ub = (size_t)u * EMB4 + lane;
    size_t vb = (size_t)v * EMB4 + lane;

    float4 a0 = g_h0[ub], a1 = g_h1[ub], a2 = g_h2[ub], a3 = g_h3[ub];
    float4 b0 = g_h0[vb], b1 = g_h1[vb], b2 = g_h2[vb], b3 = g_h3[vb];

    float sux = a0.x + a1.x + a2.x + a3.x, svx = b0.x + b1.x + b2.x + b3.x;
    float suy = a0.y + a1.y + a2.y + a3.y, svy = b0.y + b1.y + b2.y + b3.y;
    float suz = a0.z + a1.z + a2.z + a3.z, svz = b0.z + b1.z + b2.z + b3.z;
    float suw = a0.w + a1.w + a2.w + a3.w, svw = b0.w + b1.w + b2.w + b3.w;

    float d = sux * svx + suy * svy + suz * svz + suw * svw;
    #pragma unroll
    for (int off = 16; off > 0; off >>= 1)
        d += __shfl_xor_sync(0xffffffffu, d, off);

    if (lane == 0) out[w] = d * 0.0625f;   // (1/4)*(1/4)
}

// ---------------- launch ------------------------------------------------------

extern "C" void kernel_launch(void* const* d_in, const int* in_sizes, int n_in,
                              void* d_out, int out_size) {
    const float4* uE   = (const float4*)d_in[0];
    const float4* iE   = (const float4*)d_in[1];
    const float*  Lval = (const float*)d_in[2];
    const int*    Lrow = (const int*)d_in[3];
    const int*    Lcol = (const int*)d_in[4];
    const int*    uIdx = (const int*)d_in[5];
    const int*    vIdx = (const int*)d_in[6];
    float*        out  = (float*)d_out;

    int userNum = in_sizes[0] / 128;
    int itemNum = in_sizes[1] / 128;
    int n = userNum + itemNum;
    if (n > NNODES) n = NNODES;
    int e = in_sizes[2];
    if (e > MAXE) e = MAXE;
    int B = in_sizes[5];
    if (B > MAXB) B = MAXB;

    // slot 5 (profiled) = k_spmm layer 1: the hot loop
    k_zero   <<<(n + 255) / 256, 256>>>(n);                        // 0
    k_hist   <<<(e + 255) / 256, 256>>>(Lrow, e);                  // 1
    k_scan   <<<1, 1024>>>(n);                                     // 2
    k_fill   <<<(e + 255) / 256, 256>>>(Lrow, Lcol, Lval, e);      // 3
    k_init_h0<<<(n * EMB4 + 255) / 256, 256>>>(uE, iE, userNum, n);// 4

    int spmm_blocks = (n + 7) / 8;
    k_spmm<<<spmm_blocks, 256>>>(0, n);                            // 5  <- profiled
    k_spmm<<<spmm_blocks, 256>>>(1, n);                            // 6

    k_mark     <<<(B + 255) / 256, 256>>>(uIdx, vIdx, userNum, B); // 7
    k_compact  <<<(n + 255) / 256, 256>>>(n);                      // 8
    k_spmm_rows<<<(MAXROWS + 7) / 8, 256>>>();                     // 9

    k_dot<<<(B + 7) / 8, 256>>>(uIdx, vIdx, userNum, B, out);      // 10
}

// round 7
// speedup vs baseline: 1.7656x; 1.7236x over previous
#include <cuda_runtime.h>

// Problem constants (capacities for static scratch; runtime sizes used in loops)
#define NNODES 150000
#define MAXE   2000000
#define EMB4   32          // 128 floats = 32 float4 per node row
#define SCANB  1024        // scan block size
#define MAXB   16384
#define MAXROWS (2*MAXB)

// ---------------- static device scratch (sanctioned workaround) -------------
__device__ float4 g_h0[NNODES * EMB4];   // layer 0 (= feats)
__device__ float4 g_h1[NNODES * EMB4];   // layer 1
__device__ float4 g_h2[NNODES * EMB4];   // layer 2
__device__ float4 g_h3[NNODES * EMB4];   // layer 3 (only sampled rows written)
__device__ int    g_cnt[NNODES];         // per-row degree histogram
__device__ int    g_rowptr[NNODES + 1];  // CSR row pointers
__device__ int    g_cursor[NNODES];      // counting-sort cursors
__device__ int    g_cols[MAXE];          // CSR column indices
__device__ float  g_vals[MAXE];          // CSR values
__device__ int    g_partials[512];       // scan block partials
__device__ unsigned char g_need[NNODES]; // sampled-row flags
__device__ int    g_rows[MAXROWS];       // compacted needed rows
__device__ int    g_nrows;               // count of needed rows

__device__ __forceinline__ const float4* layer_buf(int i) {
    return (i == 0) ? g_h0 : (i == 1) ? g_h1 : (i == 2) ? g_h2 : g_h3;
}

// ---------------- CSR build ------------------------------------------------

__global__ void k_zero_cnt(int n) {
    int i = blockIdx.x * blockDim.x + threadIdx.x;
    if (i < n) { g_cnt[i] = 0; g_need[i] = 0; }
    if (i == 0) g_nrows = 0;
}

__global__ void k_hist(const int* __restrict__ row, int e) {
    int i = blockIdx.x * blockDim.x + threadIdx.x;
    if (i < e) atomicAdd(&g_cnt[row[i]], 1);
}

// per-block sums of g_cnt into g_partials
__global__ void k_block_sums(int n) {
    __shared__ int sh[SCANB];
    int gid = blockIdx.x * SCANB + threadIdx.x;
    sh[threadIdx.x] = (gid < n) ? g_cnt[gid] : 0;
    __syncthreads();
    for (int off = SCANB / 2; off > 0; off >>= 1) {
        if (threadIdx.x < off) sh[threadIdx.x] += sh[threadIdx.x + off];
        __syncthreads();
    }
    if (threadIdx.x == 0) g_partials[blockIdx.x] = sh[0];
}

// exclusive scan of block partials (nb <= 256), also writes g_rowptr[n] = total
__global__ void k_scan_partials(int nb, int n) {
    __shared__ int sh[257];
    int v = (threadIdx.x < nb) ? g_partials[threadIdx.x] : 0;
    sh[threadIdx.x] = v;
    __syncthreads();
    if (threadIdx.x == 0) {
        int run = 0;
        for (int i = 0; i < nb; i++) { int t = sh[i]; sh[i] = run; run += t; }
        g_rowptr[n] = run;
    }
    __syncthreads();
    if (threadIdx.x < nb) g_partials[threadIdx.x] = sh[threadIdx.x];
}

// per-block exclusive scan + partial offset -> g_rowptr, g_cursor
__global__ void k_scan_final(int n) {
    __shared__ int sh[SCANB];
    int gid = blockIdx.x * SCANB + threadIdx.x;
    int v = (gid < n) ? g_cnt[gid] : 0;
    sh[threadIdx.x] = v;
    __syncthreads();
    // Hillis-Steele inclusive scan
    for (int off = 1; off < SCANB; off <<= 1) {
        int t = (threadIdx.x >= off) ? sh[threadIdx.x - off] : 0;
        __syncthreads();
        sh[threadIdx.x] += t;
        __syncthreads();
    }
    if (gid < n) {
        int excl = sh[threadIdx.x] - v + g_partials[blockIdx.x];
        g_rowptr[gid] = excl;
        g_cursor[gid] = excl;
    }
}

// counting-sort edges into CSR slots
__global__ void k_fill(const int* __restrict__ row, const int* __restrict__ col,
                       const float* __restrict__ val, int e) {
    int i = blockIdx.x * blockDim.x + threadIdx.x;
    if (i < e) {
        int r = row[i];
        int p = atomicAdd(&g_cursor[r], 1);
        g_cols[p] = col[i];
        g_vals[p] = val[i];
    }
}

// ---------------- embeddings -----------------------------------------------

// h0 = concat(uEmbd, iEmbd), vectorized as float4
__global__ void k_init_h0(const float4* __restrict__ uE, const float4* __restrict__ iE,
                          int userNum, int n) {
    int i = blockIdx.x * blockDim.x + threadIdx.x;
    int total = n * EMB4;
    if (i < total) {
        int node = i >> 5;
        g_h0[i] = (node < userNum) ? uE[i] : iE[i - userNum * EMB4];
    }
}

// warp-per-row SpMM gather: hout[r] = sum_{e in row r} val[e] * hin[col[e]]
__global__ void k_spmm(int stage, int n) {
    const float4* __restrict__ hin = layer_buf(stage);
    float4* hout = const_cast<float4*>(layer_buf(stage + 1));

    int w    = (blockIdx.x * blockDim.x + threadIdx.x) >> 5;
    int lane = threadIdx.x & 31;
    if (w >= n) return;

    int s = g_rowptr[w];
    int e = g_rowptr[w + 1];

    float4 acc = make_float4(0.f, 0.f, 0.f, 0.f);
    for (int base = s; base < e; base += 32) {
        int idx = base + lane;
        int c = 0;
        float v = 0.f;
        if (idx < e) { c = g_cols[idx]; v = g_vals[idx]; }
        int m = min(32, e - base);
        #pragma unroll 4
        for (int j = 0; j < m; j++) {
            int   cj = __shfl_sync(0xffffffffu, c, j);
            float vj = __shfl_sync(0xffffffffu, v, j);
            float4 x = hin[cj * EMB4 + lane];
            acc.x = fmaf(vj, x.x, acc.x);
            acc.y = fmaf(vj, x.y, acc.y);
            acc.z = fmaf(vj, x.z, acc.z);
            acc.w = fmaf(vj, x.w, acc.w);
        }
    }
    hout[w * EMB4 + lane] = acc;
}

// layer-3 SpMM restricted to compacted sampled rows: g_h2 -> g_h3
__global__ void k_spmm_rows() {
    int w    = (blockIdx.x * blockDim.x + threadIdx.x) >> 5;
    int lane = threadIdx.x & 31;
    if (w >= g_nrows) return;
    int r = g_rows[w];

    int s = g_rowptr[r];
    int e = g_rowptr[r + 1];

    float4 acc = make_float4(0.f, 0.f, 0.f, 0.f);
    for (int base = s; base < e; base += 32) {
        int idx = base + lane;
        int c = 0;
        float v = 0.f;
        if (idx < e) { c = g_cols[idx]; v = g_vals[idx]; }
        int m = min(32, e - base);
        #pragma unroll 4
        for (int j = 0; j < m; j++) {
            int   cj = __shfl_sync(0xffffffffu, c, j);
            float vj = __shfl_sync(0xffffffffu, v, j);
            float4 x = g_h2[cj * EMB4 + lane];
            acc.x = fmaf(vj, x.x, acc.x);
            acc.y = fmaf(vj, x.y, acc.y);
            acc.z = fmaf(vj, x.z, acc.z);
            acc.w = fmaf(vj, x.w, acc.w);
        }
    }
    g_h3[r * EMB4 + lane] = acc;
}

// ---------------- needed-row marking / compaction ----------------------------

__global__ void k_mark(const int* __restrict__ uIdx, const int* __restrict__ vIdx,
                       int userNum, int B) {
    int i = blockIdx.x * blockDim.x + threadIdx.x;
    if (i < B) {
        g_need[uIdx[i]] = 1;
        g_need[vIdx[i] + userNum] = 1;
    }
}

__global__ void k_compact(int n) {
    int i = blockIdx.x * blockDim.x + threadIdx.x;
    int lane = threadIdx.x & 31;
    int flag = (i < n) ? (int)g_need[i] : 0;
    unsigned m = __ballot_sync(0xffffffffu, flag);
    int cnt = __popc(m);
    if (cnt == 0) return;
    int base = 0;
    if (lane == 0) base = atomicAdd(&g_nrows, cnt);
    base = __shfl_sync(0xffffffffu, base, 0);
    if (flag) g_rows[base + __popc(m & ((1u << lane) - 1u))] = i;
}

// ---------------- final dot ---------------------------------------------------

__global__ void k_dot(const int* __restrict__ uIdx, const int* __restrict__ vIdx,
                      int userNum, int B, float* __restrict__ out) {
    int w    = (blockIdx.x * blockDim.x + threadIdx.x) >> 5;
    int lane = threadIdx.x & 31;
    if (w >= B) return;

    int u = uIdx[w];
    int v = vIdx[w] + userNum;
    int ub = u * EMB4 + lane;
    int vb = v * EMB4 + lane;

    float4 a0 = g_h0[ub], a1 = g_h1[ub], a2 = g_h2[ub], a3 = g_h3[ub];
    float4 b0 = g_h0[vb], b1 = g_h1[vb], b2 = g_h2[vb], b3 = g_h3[vb];

    float sux = a0.x + a1.x + a2.x + a3.x, svx = b0.x + b1.x + b2.x + b3.x;
    float suy = a0.y + a1.y + a2.y + a3.y, svy = b0.y + b1.y + b2.y + b3.y;
    float suz = a0.z + a1.z + a2.z + a3.z, svz = b0.z + b1.z + b2.z + b3.z;
    float suw = a0.w + a1.w + a2.w + a3.w, svw = b0.w + b1.w + b2.w + b3.w;

    float d = sux * svx + suy * svy + suz * svz + suw * svw;
    #pragma unroll
    for (int off = 16; off > 0; off >>= 1)
        d += __shfl_xor_sync(0xffffffffu, d, off);

    if (lane == 0) out[w] = d * 0.0625f;   // (1/4)*(1/4) for the layer average
}

// ---------------- launch ----------------------------------------------------

extern "C" void kernel_launch(void* const* d_in, const int* in_sizes, int n_in,
                              void* d_out, int out_size) {
    const float4* uE   = (const float4*)d_in[0];
    const float4* iE   = (const float4*)d_in[1];
    const float*  Lval = (const float*)d_in[2];
    const int*    Lrow = (const int*)d_in[3];
    const int*    Lcol = (const int*)d_in[4];
    const int*    uIdx = (const int*)d_in[5];
    const int*    vIdx = (const int*)d_in[6];
    float*        out  = (float*)d_out;

    int userNum = in_sizes[0] / 128;
    int itemNum = in_sizes[1] / 128;
    int n = userNum + itemNum;
    if (n > NNODES) n = NNODES;
    int e = in_sizes[2];
    if (e > MAXE) e = MAXE;
    int B = in_sizes[5];
    if (B > MAXB) B = MAXB;

    // CSR build (R1 structure, unchanged)
    k_zero_cnt<<<(n + 255) / 256, 256>>>(n);
    k_hist<<<(e + 255) / 256, 256>>>(Lrow, e);
    int nb = (n + SCANB - 1) / SCANB;
    k_block_sums<<<nb, SCANB>>>(n);
    k_scan_partials<<<1, 256>>>(nb, n);
    k_scan_final<<<nb, SCANB>>>(n);
    k_fill<<<(e + 255) / 256, 256>>>(Lrow, Lcol, Lval, e);

    // layer 0 init
    k_init_h0<<<(n * EMB4 + 255) / 256, 256>>>(uE, iE, userNum, n);

    // needed-row marking/compaction (the ONE new variable this round)
    k_mark<<<(B + 255) / 256, 256>>>(uIdx, vIdx, userNum, B);
    k_compact<<<(n + 255) / 256, 256>>>(n);

    // 2 full SpMM layers + restricted layer 3
    int spmm_blocks = (n + 7) / 8;
    k_spmm<<<spmm_blocks, 256>>>(0, n);
    k_spmm<<<spmm_blocks, 256>>>(1, n);
    k_spmm_rows<<<(MAXROWS + 7) / 8, 256>>>();

    // final batched dot
    k_dot<<<(B + 7) / 8, 256>>>(uIdx, vIdx, userNum, B, out);
}

// round 8
// speedup vs baseline: 2.0006x; 1.1331x over previous
#include <cuda_runtime.h>
#include <cuda_fp16.h>

// Problem constants (capacities for static scratch; runtime sizes used in loops)
#define NNODES 150000
#define MAXE   2000000
#define EMB4   32          // 128 floats = 32 float4 per node row
#define EMBH   32          // 128 halfs  = 32 uint2 per node row
#define SCANB  1024        // scan block size
#define MAXB   16384
#define MAXROWS (2*MAXB)

// ---------------- static device scratch (sanctioned workaround) -------------
__device__ float4 g_h0[NNODES * EMB4];   // layer 0 fp32 (for final dot)
__device__ uint2  g_f0[NNODES * EMBH];   // layer 0 fp16 (gather source)
__device__ uint2  g_f1[NNODES * EMBH];   // layer 1 fp16
__device__ uint2  g_f2[NNODES * EMBH];   // layer 2 fp16
__device__ float4 g_h3[NNODES * EMB4];   // layer 3 fp32 (only sampled rows)
__device__ int    g_cnt[NNODES];
__device__ int    g_rowptr[NNODES + 1];
__device__ int    g_cursor[NNODES];
__device__ int    g_cols[MAXE];
__device__ float  g_vals[MAXE];
__device__ int    g_partials[512];
__device__ unsigned char g_need[NNODES];
__device__ int    g_rows[MAXROWS];
__device__ int    g_nrows;

__device__ __forceinline__ uint2* fp16_buf(int i) {
    return (i == 0) ? g_f0 : (i == 1) ? g_f1 : g_f2;
}

// ---------------- fp16 helpers ----------------------------------------------

__device__ __forceinline__ uint2 f4_to_h8(float4 a) {
    __half2 lo = __floats2half2_rn(a.x, a.y);
    __half2 hi = __floats2half2_rn(a.z, a.w);
    uint2 o;
    o.x = *reinterpret_cast<unsigned*>(&lo);
    o.y = *reinterpret_cast<unsigned*>(&hi);
    return o;
}

__device__ __forceinline__ void fma_h8(float4& acc, float v, uint2 h) {
    float2 lo = __half22float2(*reinterpret_cast<__half2*>(&h.x));
    float2 hi = __half22float2(*reinterpret_cast<__half2*>(&h.y));
    acc.x = fmaf(v, lo.x, acc.x);
    acc.y = fmaf(v, lo.y, acc.y);
    acc.z = fmaf(v, hi.x, acc.z);
    acc.w = fmaf(v, hi.y, acc.w);
}

// ---------------- CSR build (R1/R7 structure, unchanged) ---------------------

__global__ void k_zero_cnt(int n) {
    int i = blockIdx.x * blockDim.x + threadIdx.x;
    if (i < n) { g_cnt[i] = 0; g_need[i] = 0; }
    if (i == 0) g_nrows = 0;
}

__global__ void k_hist(const int* __restrict__ row, int e) {
    int i = blockIdx.x * blockDim.x + threadIdx.x;
    if (i < e) atomicAdd(&g_cnt[row[i]], 1);
}

__global__ void k_block_sums(int n) {
    __shared__ int sh[SCANB];
    int gid = blockIdx.x * SCANB + threadIdx.x;
    sh[threadIdx.x] = (gid < n) ? g_cnt[gid] : 0;
    __syncthreads();
    for (int off = SCANB / 2; off > 0; off >>= 1) {
        if (threadIdx.x < off) sh[threadIdx.x] += sh[threadIdx.x + off];
        __syncthreads();
    }
    if (threadIdx.x == 0) g_partials[blockIdx.x] = sh[0];
}

__global__ void k_scan_partials(int nb, int n) {
    __shared__ int sh[257];
    int v = (threadIdx.x < nb) ? g_partials[threadIdx.x] : 0;
    sh[threadIdx.x] = v;
    __syncthreads();
    if (threadIdx.x == 0) {
        int run = 0;
        for (int i = 0; i < nb; i++) { int t = sh[i]; sh[i] = run; run += t; }
        g_rowptr[n] = run;
    }
    __syncthreads();
    if (threadIdx.x < nb) g_partials[threadIdx.x] = sh[threadIdx.x];
}

__global__ void k_scan_final(int n) {
    __shared__ int sh[SCANB];
    int gid = blockIdx.x * SCANB + threadIdx.x;
    int v = (gid < n) ? g_cnt[gid] : 0;
    sh[threadIdx.x] = v;
    __syncthreads();
    for (int off = 1; off < SCANB; off <<= 1) {
        int t = (threadIdx.x >= off) ? sh[threadIdx.x - off] : 0;
        __syncthreads();
        sh[threadIdx.x] += t;
        __syncthreads();
    }
    if (gid < n) {
        int excl = sh[threadIdx.x] - v + g_partials[blockIdx.x];
        g_rowptr[gid] = excl;
        g_cursor[gid] = excl;
    }
}

__global__ void k_fill(const int* __restrict__ row, const int* __restrict__ col,
                       const float* __restrict__ val, int e) {
    int i = blockIdx.x * blockDim.x + threadIdx.x;
    if (i < e) {
        int r = row[i];
        int p = atomicAdd(&g_cursor[r], 1);
        g_cols[p] = col[i];
        g_vals[p] = val[i];
    }
}

// ---------------- embeddings -----------------------------------------------

// h0 = concat(uEmbd, iEmbd): fp32 copy (for dot) + fp16 copy (gather source)
__global__ void k_init_h0(const float4* __restrict__ uE, const float4* __restrict__ iE,
                          int userNum, int n) {
    int i = blockIdx.x * blockDim.x + threadIdx.x;
    int total = n * EMB4;
    if (i < total) {
        int node = i >> 5;
        float4 a = (node < userNum) ? uE[i] : iE[i - userNum * EMB4];
        g_h0[i] = a;
        g_f0[i] = f4_to_h8(a);
    }
}

// warp-per-row SpMM: fp16 gather, fp32 accumulate, fp16 store
__global__ void k_spmm(int stage, int n) {
    const uint2* __restrict__ hin = fp16_buf(stage);
    uint2* hout = fp16_buf(stage + 1);

    int w    = (blockIdx.x * blockDim.x + threadIdx.x) >> 5;
    int lane = threadIdx.x & 31;
    if (w >= n) return;

    int s = g_rowptr[w];
    int e = g_rowptr[w + 1];

    float4 acc = make_float4(0.f, 0.f, 0.f, 0.f);
    for (int base = s; base < e; base += 32) {
        int idx = base + lane;
        int c = 0;
        float v = 0.f;
        if (idx < e) { c = g_cols[idx]; v = g_vals[idx]; }
        int m = min(32, e - base);
        #pragma unroll 4
        for (int j = 0; j < m; j++) {
            int   cj = __shfl_sync(0xffffffffu, c, j);
            float vj = __shfl_sync(0xffffffffu, v, j);
            fma_h8(acc, vj, hin[cj * EMBH + lane]);
        }
    }
    hout[w * EMBH + lane] = f4_to_h8(acc);
}

// layer-3 SpMM restricted to compacted sampled rows: g_f2 -> g_h3 (fp32 out)
__global__ void k_spmm_rows() {
    int w    = (blockIdx.x * blockDim.x + threadIdx.x) >> 5;
    int lane = threadIdx.x & 31;
    if (w >= g_nrows) return;
    int r = g_rows[w];

    int s = g_rowptr[r];
    int e = g_rowptr[r + 1];

    float4 acc = make_float4(0.f, 0.f, 0.f, 0.f);
    for (int base = s; base < e; base += 32) {
        int idx = base + lane;
        int c = 0;
        float v = 0.f;
        if (idx < e) { c = g_cols[idx]; v = g_vals[idx]; }
        int m = min(32, e - base);
        #pragma unroll 4
        for (int j = 0; j < m; j++) {
            int   cj = __shfl_sync(0xffffffffu, c, j);
            float vj = __shfl_sync(0xffffffffu, v, j);
            fma_h8(acc, vj, g_f2[cj * EMBH + lane]);
        }
    }
    g_h3[r * EMB4 + lane] = acc;
}

// ---------------- needed-row marking / compaction ----------------------------

__global__ void k_mark(const int* __restrict__ uIdx, const int* __restrict__ vIdx,
                       int userNum, int B) {
    int i = blockIdx.x * blockDim.x + threadIdx.x;
    if (i < B) {
        g_need[uIdx[i]] = 1;
        g_need[vIdx[i] + userNum] = 1;
    }
}

__global__ void k_compact(int n) {
    int i = blockIdx.x * blockDim.x + threadIdx.x;
    int lane = threadIdx.x & 31;
    int flag = (i < n) ? (int)g_need[i] : 0;
    unsigned m = __ballot_sync(0xffffffffu, flag);
    int cnt = __popc(m);
    if (cnt == 0) return;
    int base = 0;
    if (lane == 0) base = atomicAdd(&g_nrows, cnt);
    base = __shfl_sync(0xffffffffu, base, 0);
    if (flag) g_rows[base + __popc(m & ((1u << lane) - 1u))] = i;
}

// ---------------- final dot ---------------------------------------------------

__global__ void k_dot(const int* __restrict__ uIdx, const int* __restrict__ vIdx,
                      int userNum, int B, float* __restrict__ out) {
    int w    = (blockIdx.x * blockDim.x + threadIdx.x) >> 5;
    int lane = threadIdx.x & 31;
    if (w >= B) return;

    int u = uIdx[w];
    int v = vIdx[w] + userNum;
    int ub4 = u * EMB4 + lane;
    int vb4 = v * EMB4 + lane;
    int ubh = u * EMBH + lane;
    int vbh = v * EMBH + lane;

    float4 su = g_h0[ub4];
    float4 sv = g_h0[vb4];
    fma_h8(su, 1.f, g_f1[ubh]);
    fma_h8(su, 1.f, g_f2[ubh]);
    fma_h8(sv, 1.f, g_f1[vbh]);
    fma_h8(sv, 1.f, g_f2[vbh]);
    float4 a3 = g_h3[ub4];
    float4 b3 = g_h3[vb4];
    su.x += a3.x; su.y += a3.y; su.z += a3.z; su.w += a3.w;
    sv.x += b3.x; sv.y += b3.y; sv.z += b3.z; sv.w += b3.w;

    float d = su.x * sv.x + su.y * sv.y + su.z * sv.z + su.w * sv.w;
    #pragma unroll
    for (int off = 16; off > 0; off >>= 1)
        d += __shfl_xor_sync(0xffffffffu, d, off);

    if (lane == 0) out[w] = d * 0.0625f;   // (1/4)*(1/4) for the layer average
}

// ---------------- launch ----------------------------------------------------

extern "C" void kernel_launch(void* const* d_in, const int* in_sizes, int n_in,
                              void* d_out, int out_size) {
    const float4* uE   = (const float4*)d_in[0];
    const float4* iE   = (const float4*)d_in[1];
    const float*  Lval = (const float*)d_in[2];
    const int*    Lrow = (const int*)d_in[3];
    const int*    Lcol = (const int*)d_in[4];
    const int*    uIdx = (const int*)d_in[5];
    const int*    vIdx = (const int*)d_in[6];
    float*        out  = (float*)d_out;

    int userNum = in_sizes[0] / 128;
    int itemNum = in_sizes[1] / 128;
    int n = userNum + itemNum;
    if (n > NNODES) n = NNODES;
    int e = in_sizes[2];
    if (e > MAXE) e = MAXE;
    int B = in_sizes[5];
    if (B > MAXB) B = MAXB;

    // CSR build (R1/R7 structure, unchanged)
    k_zero_cnt<<<(n + 255) / 256, 256>>>(n);
    k_hist<<<(e + 255) / 256, 256>>>(Lrow, e);
    int nb = (n + SCANB - 1) / SCANB;
    k_block_sums<<<nb, SCANB>>>(n);
    k_scan_partials<<<1, 256>>>(nb, n);
    k_scan_final<<<nb, SCANB>>>(n);
    k_fill<<<(e + 255) / 256, 256>>>(Lrow, Lcol, Lval, e);

    // layer 0 init (fp32 + fp16 copies)
    k_init_h0<<<(n * EMB4 + 255) / 256, 256>>>(uE, iE, userNum, n);

    // needed-row marking/compaction
    k_mark<<<(B + 255) / 256, 256>>>(uIdx, vIdx, userNum, B);
    k_compact<<<(n + 255) / 256, 256>>>(n);

    // 2 full SpMM layers (fp16 gather) + restricted layer 3
    int spmm_blocks = (n + 7) / 8;
    k_spmm<<<spmm_blocks, 256>>>(0, n);
    k_spmm<<<spmm_blocks, 256>>>(1, n);
    k_spmm_rows<<<(MAXROWS + 7) / 8, 256>>>();

    // final batched dot
    k_dot<<<(B + 7) / 8, 256>>>(uIdx, vIdx, userNum, B, out);
}

// round 9
// speedup vs baseline: 2.1327x; 1.0660x over previous
#include <cuda_runtime.h>
#include <cuda_fp16.h>

// Problem constants (capacities for static scratch; runtime sizes used in loops)
#define NNODES 150000
#define MAXE   2000000
#define EMB4   32          // 128 floats = 32 float4 per node row
#define EMBH   32          // 128 halfs  = 32 uint2 per node row
#define SCANB  1024        // scan block size
#define MAXB   16384
#define MAXROWS (2*MAXB)

// ---------------- static device scratch (sanctioned workaround) -------------
__device__ uint2  g_f0[NNODES * EMBH];   // layer 0 fp16 (gather source)
__device__ uint2  g_f1[NNODES * EMBH];   // layer 1 fp16
__device__ uint2  g_f2[NNODES * EMBH];   // layer 2 fp16
__device__ float4 g_h3[NNODES * EMB4];   // layer 3 fp32 (only sampled rows)
__device__ int    g_cnt[NNODES];
__device__ int    g_rowptr[NNODES + 1];
__device__ int    g_cursor[NNODES];
__device__ int2   g_edge[MAXE];          // fused CSR {col, val-bits}
__device__ int    g_partials[512];
__device__ unsigned char g_need[NNODES];
__device__ int    g_rows[MAXROWS];
__device__ int    g_nrows;

__device__ __forceinline__ uint2* fp16_buf(int i) {
    return (i == 0) ? g_f0 : (i == 1) ? g_f1 : g_f2;
}

// ---------------- fp16 helpers ----------------------------------------------

__device__ __forceinline__ uint2 f4_to_h8(float4 a) {
    __half2 lo = __floats2half2_rn(a.x, a.y);
    __half2 hi = __floats2half2_rn(a.z, a.w);
    uint2 o;
    o.x = *reinterpret_cast<unsigned*>(&lo);
    o.y = *reinterpret_cast<unsigned*>(&hi);
    return o;
}

__device__ __forceinline__ void fma_h8(float4& acc, float v, uint2 h) {
    float2 lo = __half22float2(*reinterpret_cast<__half2*>(&h.x));
    float2 hi = __half22float2(*reinterpret_cast<__half2*>(&h.y));
    acc.x = fmaf(v, lo.x, acc.x);
    acc.y = fmaf(v, lo.y, acc.y);
    acc.z = fmaf(v, hi.x, acc.z);
    acc.w = fmaf(v, hi.y, acc.w);
}

// ---------------- CSR build (R1/R7 structure) ---------------------------------

__global__ void k_zero_cnt(int n) {
    int i = blockIdx.x * blockDim.x + threadIdx.x;
    if (i < n) { g_cnt[i] = 0; g_need[i] = 0; }
    if (i == 0) g_nrows = 0;
}

__global__ void k_hist(const int* __restrict__ row, int e) {
    int i = blockIdx.x * blockDim.x + threadIdx.x;
    if (i < e) atomicAdd(&g_cnt[row[i]], 1);
}

__global__ void k_block_sums(int n) {
    __shared__ int sh[SCANB];
    int gid = blockIdx.x * SCANB + threadIdx.x;
    sh[threadIdx.x] = (gid < n) ? g_cnt[gid] : 0;
    __syncthreads();
    for (int off = SCANB / 2; off > 0; off >>= 1) {
        if (threadIdx.x < off) sh[threadIdx.x] += sh[threadIdx.x + off];
        __syncthreads();
    }
    if (threadIdx.x == 0) g_partials[blockIdx.x] = sh[0];
}

__global__ void k_scan_partials(int nb, int n) {
    __shared__ int sh[257];
    int v = (threadIdx.x < nb) ? g_partials[threadIdx.x] : 0;
    sh[threadIdx.x] = v;
    __syncthreads();
    if (threadIdx.x == 0) {
        int run = 0;
        for (int i = 0; i < nb; i++) { int t = sh[i]; sh[i] = run; run += t; }
        g_rowptr[n] = run;
    }
    __syncthreads();
    if (threadIdx.x < nb) g_partials[threadIdx.x] = sh[threadIdx.x];
}

__global__ void k_scan_final(int n) {
    __shared__ int sh[SCANB];
    int gid = blockIdx.x * SCANB + threadIdx.x;
    int v = (gid < n) ? g_cnt[gid] : 0;
    sh[threadIdx.x] = v;
    __syncthreads();
    for (int off = 1; off < SCANB; off <<= 1) {
        int t = (threadIdx.x >= off) ? sh[threadIdx.x - off] : 0;
        __syncthreads();
        sh[threadIdx.x] += t;
        __syncthreads();
    }
    if (gid < n) {
        int excl = sh[threadIdx.x] - v + g_partials[blockIdx.x];
        g_rowptr[gid] = excl;
        g_cursor[gid] = excl;
    }
}

// counting-sort edges into fused int2 CSR slots (one 8B store per edge)
__global__ void k_fill(const int* __restrict__ row, const int* __restrict__ col,
                       const float* __restrict__ val, int e) {
    int i = blockIdx.x * blockDim.x + threadIdx.x;
    if (i < e) {
        int r = row[i];
        int p = atomicAdd(&g_cursor[r], 1);
        g_edge[p] = make_int2(col[i], __float_as_int(val[i]));
    }
}

// ---------------- embeddings -----------------------------------------------

// h0 fp16 gather copy only (fp32 h0 read directly from inputs in k_dot)
__global__ void k_init_h0(const float4* __restrict__ uE, const float4* __restrict__ iE,
                          int userNum, int n) {
    int i = blockIdx.x * blockDim.x + threadIdx.x;
    int total = n * EMB4;
    if (i < total) {
        int node = i >> 5;
        float4 a = (node < userNum) ? uE[i] : iE[i - userNum * EMB4];
        g_f0[i] = f4_to_h8(a);
    }
}

// warp-per-row SpMM: fp16 gather, fp32 accumulate, fp16 store
__global__ void k_spmm(int stage, int n) {
    const uint2* __restrict__ hin = fp16_buf(stage);
    uint2* hout = fp16_buf(stage + 1);

    int w    = (blockIdx.x * blockDim.x + threadIdx.x) >> 5;
    int lane = threadIdx.x & 31;
    if (w >= n) return;

    int s = g_rowptr[w];
    int e = g_rowptr[w + 1];

    float4 acc = make_float4(0.f, 0.f, 0.f, 0.f);
    for (int base = s; base < e; base += 32) {
        int idx = base + lane;
        int2 ed = (idx < e) ? g_edge[idx] : make_int2(0, 0);
        int m = min(32, e - base);
        #pragma unroll 4
        for (int j = 0; j < m; j++) {
            int   cj = __shfl_sync(0xffffffffu, ed.x, j);
            float vj = __shfl_sync(0xffffffffu, __int_as_float(ed.y), j);
            fma_h8(acc, vj, hin[cj * EMBH + lane]);
        }
    }
    hout[w * EMBH + lane] = f4_to_h8(acc);
}

// layer-3 SpMM restricted to compacted sampled rows: g_f2 -> g_h3 (fp32 out)
__global__ void k_spmm_rows() {
    int w    = (blockIdx.x * blockDim.x + threadIdx.x) >> 5;
    int lane = threadIdx.x & 31;
    if (w >= g_nrows) return;
    int r = g_rows[w];

    int s = g_rowptr[r];
    int e = g_rowptr[r + 1];

    float4 acc = make_float4(0.f, 0.f, 0.f, 0.f);
    for (int base = s; base < e; base += 32) {
        int idx = base + lane;
        int2 ed = (idx < e) ? g_edge[idx] : make_int2(0, 0);
        int m = min(32, e - base);
        #pragma unroll 4
        for (int j = 0; j < m; j++) {
            int   cj = __shfl_sync(0xffffffffu, ed.x, j);
            float vj = __shfl_sync(0xffffffffu, __int_as_float(ed.y), j);
            fma_h8(acc, vj, g_f2[cj * EMBH + lane]);
        }
    }
    g_h3[r * EMB4 + lane] = acc;
}

// ---------------- needed-row marking / compaction ----------------------------

__global__ void k_mark(const int* __restrict__ uIdx, const int* __restrict__ vIdx,
                       int userNum, int B) {
    int i = blockIdx.x * blockDim.x + threadIdx.x;
    if (i < B) {
        g_need[uIdx[i]] = 1;
        g_need[vIdx[i] + userNum] = 1;
    }
}

__global__ void k_compact(int n) {
    int i = blockIdx.x * blockDim.x + threadIdx.x;
    int lane = threadIdx.x & 31;
    int flag = (i < n) ? (int)g_need[i] : 0;
    unsigned m = __ballot_sync(0xffffffffu, flag);
    int cnt = __popc(m);
    if (cnt == 0) return;
    int base = 0;
    if (lane == 0) base = atomicAdd(&g_nrows, cnt);
    base = __shfl_sync(0xffffffffu, base, 0);
    if (flag) g_rows[base + __popc(m & ((1u << lane) - 1u))] = i;
}

// ---------------- final dot ---------------------------------------------------

__global__ void k_dot(const float4* __restrict__ uE, const float4* __restrict__ iE,
                      const int* __restrict__ uIdx, const int* __restrict__ vIdx,
                      int userNum, int B, float* __restrict__ out) {
    int w    = (blockIdx.x * blockDim.x + threadIdx.x) >> 5;
    int lane = threadIdx.x & 31;
    if (w >= B) return;

    int u  = uIdx[w];
    int vi = vIdx[w];
    int v  = vi + userNum;
    int ub4 = u * EMB4 + lane;
    int vb4 = v * EMB4 + lane;
    int ubh = u * EMBH + lane;
    int vbh = v * EMBH + lane;

    float4 su = uE[ub4];                       // layer 0 fp32 from input
    float4 sv = iE[vi * EMB4 + lane];
    fma_h8(su, 1.f, g_f1[ubh]);
    fma_h8(su, 1.f, g_f2[ubh]);
    fma_h8(sv, 1.f, g_f1[vbh]);
    fma_h8(sv, 1.f, g_f2[vbh]);
    float4 a3 = g_h3[ub4];
    float4 b3 = g_h3[vb4];
    su.x += a3.x; su.y += a3.y; su.z += a3.z; su.w += a3.w;
    sv.x += b3.x; sv.y += b3.y; sv.z += b3.z; sv.w += b3.w;

    float d = su.x * sv.x + su.y * sv.y + su.z * sv.z + su.w * sv.w;
    #pragma unroll
    for (int off = 16; off > 0; off >>= 1)
        d += __shfl_xor_sync(0xffffffffu, d, off);

    if (lane == 0) out[w] = d * 0.0625f;   // (1/4)*(1/4) for the layer average
}

// ---------------- launch ----------------------------------------------------

extern "C" void kernel_launch(void* const* d_in, const int* in_sizes, int n_in,
                              void* d_out, int out_size) {
    const float4* uE   = (const float4*)d_in[0];
    const float4* iE   = (const float4*)d_in[1];
    const float*  Lval = (const float*)d_in[2];
    const int*    Lrow = (const int*)d_in[3];
    const int*    Lcol = (const int*)d_in[4];
    const int*    uIdx = (const int*)d_in[5];
    const int*    vIdx = (const int*)d_in[6];
    float*        out  = (float*)d_out;

    int userNum = in_sizes[0] / 128;
    int itemNum = in_sizes[1] / 128;
    int n = userNum + itemNum;
    if (n > NNODES) n = NNODES;
    int e = in_sizes[2];
    if (e > MAXE) e = MAXE;
    int B = in_sizes[5];
    if (B > MAXB) B = MAXB;

    // CSR build (R1/R7 structure)
    k_zero_cnt<<<(n + 255) / 256, 256>>>(n);
    k_hist<<<(e + 255) / 256, 256>>>(Lrow, e);
    int nb = (n + SCANB - 1) / SCANB;
    k_block_sums<<<nb, SCANB>>>(n);
    k_scan_partials<<<1, 256>>>(nb, n);
    k_scan_final<<<nb, SCANB>>>(n);
    k_fill<<<(e + 255) / 256, 256>>>(Lrow, Lcol, Lval, e);

    // layer 0 init (fp16 gather copy only)
    k_init_h0<<<(n * EMB4 + 255) / 256, 256>>>(uE, iE, userNum, n);

    // needed-row marking/compaction
    k_mark<<<(B + 255) / 256, 256>>>(uIdx, vIdx, userNum, B);
    k_compact<<<(n + 255) / 256, 256>>>(n);

    // 2 full SpMM layers (fp16 gather) + restricted layer 3
    int spmm_blocks = (n + 7) / 8;
    k_spmm<<<spmm_blocks, 256>>>(0, n);
    k_spmm<<<spmm_blocks, 256>>>(1, n);
    k_spmm_rows<<<(MAXROWS + 7) / 8, 256>>>();

    // final batched dot
    k_dot<<<(B + 7) / 8, 256>>>(uE, iE, uIdx, vIdx, userNum, B, out);
}

// round 10
// speedup vs baseline: 2.2648x; 1.0619x over previous
#include <cuda_runtime.h>
#include <cuda_fp16.h>

// Problem constants (capacities for static scratch; runtime sizes used in loops)
#define NNODES 150000
#define MAXE   2000000
#define EMB4   32          // 128 floats = 32 float4 per node row
#define EMBH   32          // 128 halfs  = 32 uint2 per node row
#define SCANB  1024        // scan block size
#define MAXB   16384

// ---------------- static device scratch (sanctioned workaround) -------------
__device__ uint2  g_f0[NNODES * EMBH];   // layer 0 fp16 (gather source)
__device__ uint2  g_f1[NNODES * EMBH];   // layer 1 fp16
__device__ uint2  g_f2[NNODES * EMBH];   // layer 2 fp16
__device__ uint2  g_f3[NNODES * EMBH];   // layer 3 fp16 (only sampled rows)
__device__ int    g_cnt[NNODES];
__device__ int    g_rowptr[NNODES + 1];
__device__ int    g_cursor[NNODES];
__device__ int2   g_edge[MAXE];          // fused CSR {col, val-bits}
__device__ int    g_partials[512];

__device__ __forceinline__ uint2* fp16_buf(int i) {
    return (i == 0) ? g_f0 : (i == 1) ? g_f1 : (i == 2) ? g_f2 : g_f3;
}

// ---------------- fp16 helpers ----------------------------------------------

__device__ __forceinline__ uint2 f4_to_h8(float4 a) {
    __half2 lo = __floats2half2_rn(a.x, a.y);
    __half2 hi = __floats2half2_rn(a.z, a.w);
    uint2 o;
    o.x = *reinterpret_cast<unsigned*>(&lo);
    o.y = *reinterpret_cast<unsigned*>(&hi);
    return o;
}

__device__ __forceinline__ void fma_h8(float4& acc, float v, uint2 h) {
    float2 lo = __half22float2(*reinterpret_cast<__half2*>(&h.x));
    float2 hi = __half22float2(*reinterpret_cast<__half2*>(&h.y));
    acc.x = fmaf(v, lo.x, acc.x);
    acc.y = fmaf(v, lo.y, acc.y);
    acc.z = fmaf(v, hi.x, acc.z);
    acc.w = fmaf(v, hi.y, acc.w);
}

// ---------------- layer 0 init + counter zero (fused) ------------------------

__global__ void k_init(const float4* __restrict__ uE, const float4* __restrict__ iE,
                       int userNum, int n) {
    int i = blockIdx.x * blockDim.x + threadIdx.x;
    int total = n * EMB4;
    if (i < total) {
        int node = i >> 5;
        float4 a = (node < userNum) ? uE[i] : iE[i - userNum * EMB4];
        g_f0[i] = f4_to_h8(a);
    }
    if (i < n) g_cnt[i] = 0;   // fused histogram zeroing
}

// ---------------- CSR build ---------------------------------------------------

__global__ void k_hist(const int* __restrict__ row, int e) {
    int i = blockIdx.x * blockDim.x + threadIdx.x;
    if (i < e) atomicAdd(&g_cnt[row[i]], 1);
}

// per-block sums of g_cnt into g_partials
__global__ void k_block_sums(int n) {
    __shared__ int sh[SCANB];
    int gid = blockIdx.x * SCANB + threadIdx.x;
    sh[threadIdx.x] = (gid < n) ? g_cnt[gid] : 0;
    __syncthreads();
    for (int off = SCANB / 2; off > 0; off >>= 1) {
        if (threadIdx.x < off) sh[threadIdx.x] += sh[threadIdx.x + off];
        __syncthreads();
    }
    if (threadIdx.x == 0) g_partials[blockIdx.x] = sh[0];
}

// fused partial-offset + per-block exclusive scan -> g_rowptr, g_cursor.
// Every block redundantly reduces the <=512 partials to get its own offset
// (parallel across blocks; replaces the separate serial partials-scan kernel).
__global__ void k_scan_apply(int nb, int n) {
    __shared__ int sh[SCANB];
    __shared__ int red_off[32], red_tot[32];
    __shared__ int s_off, s_tot;
    int t = threadIdx.x;

    // offset = sum partials[j < blockIdx.x];  total = sum all partials
    int p  = (t < nb) ? g_partials[t] : 0;
    int po = (t < (int)blockIdx.x) ? p : 0;
    #pragma unroll
    for (int o = 16; o > 0; o >>= 1) {
        po += __shfl_down_sync(0xffffffffu, po, o);
        p  += __shfl_down_sync(0xffffffffu, p,  o);
    }
    if ((t & 31) == 0) { red_off[t >> 5] = po; red_tot[t >> 5] = p; }
    __syncthreads();
    if (t < 32) {
        int nw = SCANB >> 5;
        int a = (t < nw) ? red_off[t] : 0;
        int b = (t < nw) ? red_tot[t] : 0;
        #pragma unroll
        for (int o = 16; o > 0; o >>= 1) {
            a += __shfl_down_sync(0xffffffffu, a, o);
            b += __shfl_down_sync(0xffffffffu, b, o);
        }
        if (t == 0) { s_off = a; s_tot = b; }
    }
    __syncthreads();

    // per-block inclusive scan (Hillis-Steele), then exclusive + offset
    int gid = blockIdx.x * SCANB + t;
    int v = (gid < n) ? g_cnt[gid] : 0;
    sh[t] = v;
    __syncthreads();
    for (int off = 1; off < SCANB; off <<= 1) {
        int tv = (t >= off) ? sh[t - off] : 0;
        __syncthreads();
        sh[t] += tv;
        __syncthreads();
    }
    if (gid < n) {
        int excl = sh[t] - v + s_off;
        g_rowptr[gid] = excl;
        g_cursor[gid] = excl;
    }
    if (blockIdx.x == 0 && t == 0) g_rowptr[n] = s_tot;
}

// counting-sort edges into fused int2 CSR slots (one 8B store per edge)
__global__ void k_fill(const int* __restrict__ row, const int* __restrict__ col,
                       const float* __restrict__ val, int e) {
    int i = blockIdx.x * blockDim.x + threadIdx.x;
    if (i < e) {
        int r = row[i];
        int p = atomicAdd(&g_cursor[r], 1);
        g_edge[p] = make_int2(col[i], __float_as_int(val[i]));
    }
}

// ---------------- SpMM (warp per row, fp16 gather / fp32 accum) ---------------

__device__ __forceinline__ float4 row_gather(const uint2* __restrict__ hin,
                                             int s, int e, int lane) {
    float4 acc = make_float4(0.f, 0.f, 0.f, 0.f);
    for (int base = s; base < e; base += 32) {
        int idx = base + lane;
        int2 ed = (idx < e) ? g_edge[idx] : make_int2(0, 0);
        int m = min(32, e - base);
        #pragma unroll 4
        for (int j = 0; j < m; j++) {
            int   cj = __shfl_sync(0xffffffffu, ed.x, j);
            float vj = __shfl_sync(0xffffffffu, __int_as_float(ed.y), j);
            fma_h8(acc, vj, hin[cj * EMBH + lane]);
        }
    }
    return acc;
}

__global__ void k_spmm(int stage, int n) {
    const uint2* __restrict__ hin = fp16_buf(stage);
    uint2* hout = fp16_buf(stage + 1);
    int w    = (blockIdx.x * blockDim.x + threadIdx.x) >> 5;
    int lane = threadIdx.x & 31;
    if (w >= n) return;
    float4 acc = row_gather(hin, g_rowptr[w], g_rowptr[w + 1], lane);
    hout[w * EMBH + lane] = f4_to_h8(acc);
}

// layer-3 SpMM over sampled rows directly (duplicates recompute identical
// values and race benignly on identical writes — deterministic)
__global__ void k_spmm3(const int* __restrict__ uIdx, const int* __restrict__ vIdx,
                        int userNum, int B) {
    int w    = (blockIdx.x * blockDim.x + threadIdx.x) >> 5;
    int lane = threadIdx.x & 31;
    if (w >= 2 * B) return;
    int r = (w < B) ? uIdx[w] : (vIdx[w - B] + userNum);
    float4 acc = row_gather(g_f2, g_rowptr[r], g_rowptr[r + 1], lane);
    g_f3[r * EMBH + lane] = f4_to_h8(acc);
}

// ---------------- final dot ---------------------------------------------------

__global__ void k_dot(const float4* __restrict__ uE, const float4* __restrict__ iE,
                      const int* __restrict__ uIdx, const int* __restrict__ vIdx,
                      int userNum, int B, float* __restrict__ out) {
    int w    = (blockIdx.x * blockDim.x + threadIdx.x) >> 5;
    int lane = threadIdx.x & 31;
    if (w >= B) return;

    int u  = uIdx[w];
    int vi = vIdx[w];
    int v  = vi + userNum;
    int ubh = u * EMBH + lane;
    int vbh = v * EMBH + lane;

    float4 su = uE[u * EMB4 + lane];           // layer 0 fp32 from input
    float4 sv = iE[vi * EMB4 + lane];
    fma_h8(su, 1.f, g_f1[ubh]);
    fma_h8(su, 1.f, g_f2[ubh]);
    fma_h8(su, 1.f, g_f3[ubh]);
    fma_h8(sv, 1.f, g_f1[vbh]);
    fma_h8(sv, 1.f, g_f2[vbh]);
    fma_h8(sv, 1.f, g_f3[vbh]);

    float d = su.x * sv.x + su.y * sv.y + su.z * sv.z + su.w * sv.w;
    #pragma unroll
    for (int off = 16; off > 0; off >>= 1)
        d += __shfl_xor_sync(0xffffffffu, d, off);

    if (lane == 0) out[w] = d * 0.0625f;   // (1/4)*(1/4) for the layer average
}

// ---------------- launch ----------------------------------------------------

extern "C" void kernel_launch(void* const* d_in, const int* in_sizes, int n_in,
                              void* d_out, int out_size) {
    const float4* uE   = (const float4*)d_in[0];
    const float4* iE   = (const float4*)d_in[1];
    const float*  Lval = (const float*)d_in[2];
    const int*    Lrow = (const int*)d_in[3];
    const int*    Lcol = (const int*)d_in[4];
    const int*    uIdx = (const int*)d_in[5];
    const int*    vIdx = (const int*)d_in[6];
    float*        out  = (float*)d_out;

    int userNum = in_sizes[0] / 128;
    int itemNum = in_sizes[1] / 128;
    int n = userNum + itemNum;
    if (n > NNODES) n = NNODES;
    int e = in_sizes[2];
    if (e > MAXE) e = MAXE;
    int B = in_sizes[5];
    if (B > MAXB) B = MAXB;

    int nb = (n + SCANB - 1) / SCANB;
    int spmm_blocks = (n + 7) / 8;

    k_init      <<<(n * EMB4 + 255) / 256, 256>>>(uE, iE, userNum, n); // 0
    k_hist      <<<(e + 255) / 256, 256>>>(Lrow, e);                   // 1
    k_block_sums<<<nb, SCANB>>>(n);                                    // 2
    k_scan_apply<<<nb, SCANB>>>(nb, n);                                // 3
    k_fill      <<<(e + 255) / 256, 256>>>(Lrow, Lcol, Lval, e);       // 4
    k_spmm      <<<spmm_blocks, 256>>>(0, n);                          // 5
    k_spmm      <<<spmm_blocks, 256>>>(1, n);                          // 6
    k_spmm3     <<<(2 * B + 7) / 8, 256>>>(uIdx, vIdx, userNum, B);    // 7
    k_dot       <<<(B + 7) / 8, 256>>>(uE, iE, uIdx, vIdx, userNum, B, out); // 8
}